// round 3
// baseline (speedup 1.0000x reference)
#include <cuda_runtime.h>
#include <cstdint>

// ---------------------------------------------------------------------------
// Fused 4-head attention, N=8192, D=256, HD=64, TF32 mma.sync path.
// Stage 1: QKV projections (TF32 GEMM)  -> g_Q/g_K/g_V
// Stage 2: flash attention per (head, 128-query tile) -> g_AO
// Stage 3: output projection (same GEMM) -> d_out
// ---------------------------------------------------------------------------

#define NTOK 8192
#define DMODEL 256

__device__ float g_Q[NTOK * DMODEL];
__device__ float g_K[NTOK * DMODEL];
__device__ float g_V[NTOK * DMODEL];
__device__ float g_AO[NTOK * DMODEL];

__device__ __forceinline__ uint32_t f2tf(float f) {
    uint32_t r;
    asm("cvt.rna.tf32.f32 %0, %1;" : "=r"(r) : "f"(f));
    return r;
}

__device__ __forceinline__ void mma8(float* c,
                                     uint32_t a0, uint32_t a1, uint32_t a2, uint32_t a3,
                                     uint32_t b0, uint32_t b1) {
    asm("mma.sync.aligned.m16n8k8.row.col.f32.tf32.tf32.f32 "
        "{%0,%1,%2,%3}, {%4,%5,%6,%7}, {%8,%9}, {%0,%1,%2,%3};"
        : "+f"(c[0]), "+f"(c[1]), "+f"(c[2]), "+f"(c[3])
        : "r"(a0), "r"(a1), "r"(a2), "r"(a3), "r"(b0), "r"(b1));
}

// ---------------------------------------------------------------------------
// Generic C[M,256] = A[M,256] @ W[256,256] + bias, TF32, tile 128x64x32.
// Block = 256 threads (8 warps), warp w owns m-rows [16w, 16w+16), all 64 n.
// ---------------------------------------------------------------------------
__device__ __forceinline__ void gemm256(const float* __restrict__ A,
                                        const float* __restrict__ W,
                                        const float* __restrict__ bias,
                                        float* __restrict__ C) {
    __shared__ uint32_t As[128 * 36];   // [m][k], stride 36 (conflict-free frag reads)
    __shared__ uint32_t Ws[32 * 68];    // [k][n], stride 68

    const int tid = threadIdx.x;
    const int lane = tid & 31;
    const int w = tid >> 5;
    const int g = lane >> 2;   // groupID (row within frag)
    const int t = lane & 3;    // threadID in group
    const int m0 = blockIdx.x * 128;
    const int n0 = blockIdx.y * 64;

    float acc[8][4];
#pragma unroll
    for (int nt = 0; nt < 8; nt++)
#pragma unroll
        for (int i = 0; i < 4; i++) acc[nt][i] = 0.f;

    for (int kc = 0; kc < 256; kc += 32) {
        __syncthreads();
        // A tile: 128x32 -> 1024 float4, 4 per thread
#pragma unroll
        for (int r = 0; r < 4; r++) {
            int idx = tid + r * 256;
            int row = idx >> 3;
            int c4 = (idx & 7) * 4;
            float4 v = *(const float4*)(A + (m0 + row) * 256 + kc + c4);
            uint32_t* d = &As[row * 36 + c4];
            d[0] = f2tf(v.x); d[1] = f2tf(v.y); d[2] = f2tf(v.z); d[3] = f2tf(v.w);
        }
        // W tile: 32x64 -> 512 float4, 2 per thread
#pragma unroll
        for (int r = 0; r < 2; r++) {
            int idx = tid + r * 256;
            int kr = idx >> 4;
            int c4 = (idx & 15) * 4;
            float4 v = *(const float4*)(W + (kc + kr) * 256 + n0 + c4);
            uint32_t* d = &Ws[kr * 68 + c4];
            d[0] = f2tf(v.x); d[1] = f2tf(v.y); d[2] = f2tf(v.z); d[3] = f2tf(v.w);
        }
        __syncthreads();

#pragma unroll
        for (int kt = 0; kt < 4; kt++) {
            uint32_t a0 = As[(w * 16 + g) * 36 + kt * 8 + t];
            uint32_t a1 = As[(w * 16 + g + 8) * 36 + kt * 8 + t];
            uint32_t a2 = As[(w * 16 + g) * 36 + kt * 8 + t + 4];
            uint32_t a3 = As[(w * 16 + g + 8) * 36 + kt * 8 + t + 4];
#pragma unroll
            for (int nt = 0; nt < 8; nt++) {
                uint32_t b0 = Ws[(kt * 8 + t) * 68 + nt * 8 + g];
                uint32_t b1 = Ws[(kt * 8 + t + 4) * 68 + nt * 8 + g];
                mma8(acc[nt], a0, a1, a2, a3, b0, b1);
            }
        }
    }

    const int r0 = m0 + w * 16 + g;
#pragma unroll
    for (int nt = 0; nt < 8; nt++) {
        int col = n0 + nt * 8 + 2 * t;
        float bv0 = bias[col], bv1 = bias[col + 1];
        float2 v0 = make_float2(acc[nt][0] + bv0, acc[nt][1] + bv1);
        float2 v1 = make_float2(acc[nt][2] + bv0, acc[nt][3] + bv1);
        *(float2*)(C + r0 * 256 + col) = v0;
        *(float2*)(C + (r0 + 8) * 256 + col) = v1;
    }
}

__global__ void __launch_bounds__(256) qkv_kernel(const float* __restrict__ x,
                                                  const float* __restrict__ Wq, const float* __restrict__ bq,
                                                  const float* __restrict__ Wk, const float* __restrict__ bk,
                                                  const float* __restrict__ Wv, const float* __restrict__ bv) {
    if (blockIdx.z == 0)      gemm256(x, Wq, bq, g_Q);
    else if (blockIdx.z == 1) gemm256(x, Wk, bk, g_K);
    else                      gemm256(x, Wv, bv, g_V);
}

__global__ void __launch_bounds__(256) oproj_kernel(const float* __restrict__ Wo,
                                                    const float* __restrict__ bo,
                                                    float* __restrict__ out) {
    gemm256(g_AO, Wo, bo, out);
}

// ---------------------------------------------------------------------------
// Flash attention. Block = (128 queries, 1 head), 8 warps, each warp 16 rows.
// Key loop in 64-key chunks. Q frags live in registers for the whole kernel.
// ---------------------------------------------------------------------------
__global__ void __launch_bounds__(256) attn_kernel() {
    __shared__ uint32_t Ks[64 * 68];   // [j][d], stride 68
    __shared__ uint32_t Vs[64 * 68];   // [j][d], stride 68

    const int tid = threadIdx.x;
    const int lane = tid & 31;
    const int w = tid >> 5;
    const int g = lane >> 2;
    const int t = lane & 3;
    const int q0 = blockIdx.x * 128;
    const int h = blockIdx.y;
    const int colbase = h * 64;
    const int mrow = q0 + w * 16 + g;

    // Q fragments (scale 1/sqrt(64)=0.125 folded in): A layout m16n8k8
    uint32_t qf[8][4];
#pragma unroll
    for (int kt = 0; kt < 8; kt++) {
        int c = colbase + kt * 8 + t;
        qf[kt][0] = f2tf(g_Q[mrow * 256 + c] * 0.125f);
        qf[kt][1] = f2tf(g_Q[(mrow + 8) * 256 + c] * 0.125f);
        qf[kt][2] = f2tf(g_Q[mrow * 256 + c + 4] * 0.125f);
        qf[kt][3] = f2tf(g_Q[(mrow + 8) * 256 + c + 4] * 0.125f);
    }

    float o[8][4];
#pragma unroll
    for (int dt = 0; dt < 8; dt++)
#pragma unroll
        for (int i = 0; i < 4; i++) o[dt][i] = 0.f;

    float m_lo = -1e30f, m_hi = -1e30f, l_lo = 0.f, l_hi = 0.f;

    const int srcA = (lane & ~3) | (t >> 1);  // owner of cols {t}
    const int srcB = srcA + 2;                // owner of cols {t+4}

    for (int j0 = 0; j0 < NTOK; j0 += 64) {
        __syncthreads();
        // Stage K and V 64x64 tiles (cvt to tf32 on the way in)
#pragma unroll
        for (int r = 0; r < 4; r++) {
            int idx = tid + r * 256;
            int row = idx >> 4;
            int c4 = (idx & 15) * 4;
            float4 kv = *(const float4*)(g_K + (j0 + row) * 256 + colbase + c4);
            uint32_t* dk = &Ks[row * 68 + c4];
            dk[0] = f2tf(kv.x); dk[1] = f2tf(kv.y); dk[2] = f2tf(kv.z); dk[3] = f2tf(kv.w);
            float4 vv = *(const float4*)(g_V + (j0 + row) * 256 + colbase + c4);
            uint32_t* dv = &Vs[row * 68 + c4];
            dv[0] = f2tf(vv.x); dv[1] = f2tf(vv.y); dv[2] = f2tf(vv.z); dv[3] = f2tf(vv.w);
        }
        __syncthreads();

        // S = Q K^T  (n = key j, k = head dim d); B(k,n) = K[n][k] = Ks[j][d]
        float s[8][4];
#pragma unroll
        for (int nt = 0; nt < 8; nt++)
#pragma unroll
            for (int i = 0; i < 4; i++) s[nt][i] = 0.f;

#pragma unroll
        for (int kt = 0; kt < 8; kt++) {
#pragma unroll
            for (int nt = 0; nt < 8; nt++) {
                uint32_t b0 = Ks[(nt * 8 + g) * 68 + kt * 8 + t];
                uint32_t b1 = Ks[(nt * 8 + g) * 68 + kt * 8 + t + 4];
                mma8(s[nt], qf[kt][0], qf[kt][1], qf[kt][2], qf[kt][3], b0, b1);
            }
        }

        // Online softmax (rows lo = g, hi = g+8; stats within a quad)
        float rmax_lo = -1e30f, rmax_hi = -1e30f;
#pragma unroll
        for (int nt = 0; nt < 8; nt++) {
            rmax_lo = fmaxf(rmax_lo, fmaxf(s[nt][0], s[nt][1]));
            rmax_hi = fmaxf(rmax_hi, fmaxf(s[nt][2], s[nt][3]));
        }
        rmax_lo = fmaxf(rmax_lo, __shfl_xor_sync(0xffffffffu, rmax_lo, 1));
        rmax_lo = fmaxf(rmax_lo, __shfl_xor_sync(0xffffffffu, rmax_lo, 2));
        rmax_hi = fmaxf(rmax_hi, __shfl_xor_sync(0xffffffffu, rmax_hi, 1));
        rmax_hi = fmaxf(rmax_hi, __shfl_xor_sync(0xffffffffu, rmax_hi, 2));

        float mn_lo = fmaxf(m_lo, rmax_lo);
        float mn_hi = fmaxf(m_hi, rmax_hi);
        float f_lo = __expf(m_lo - mn_lo);
        float f_hi = __expf(m_hi - mn_hi);
        m_lo = mn_lo; m_hi = mn_hi;

        float rs_lo = 0.f, rs_hi = 0.f;
#pragma unroll
        for (int nt = 0; nt < 8; nt++) {
            s[nt][0] = __expf(s[nt][0] - m_lo);
            s[nt][1] = __expf(s[nt][1] - m_lo);
            s[nt][2] = __expf(s[nt][2] - m_hi);
            s[nt][3] = __expf(s[nt][3] - m_hi);
            rs_lo += s[nt][0] + s[nt][1];
            rs_hi += s[nt][2] + s[nt][3];
        }
        rs_lo += __shfl_xor_sync(0xffffffffu, rs_lo, 1);
        rs_lo += __shfl_xor_sync(0xffffffffu, rs_lo, 2);
        rs_hi += __shfl_xor_sync(0xffffffffu, rs_hi, 1);
        rs_hi += __shfl_xor_sync(0xffffffffu, rs_hi, 2);
        l_lo = l_lo * f_lo + rs_lo;
        l_hi = l_hi * f_hi + rs_hi;

#pragma unroll
        for (int dt = 0; dt < 8; dt++) {
            o[dt][0] *= f_lo; o[dt][1] *= f_lo;
            o[dt][2] *= f_hi; o[dt][3] *= f_hi;
        }

        // P(C-layout) -> A-fragments via intra-quad shuffles, then O += P V.
        // B(k=j, n=d) = V[j][d] = Vs (read transposed in-place).
        const bool odd = (t & 1);
#pragma unroll
        for (int kt = 0; kt < 8; kt++) {
            float x0 = __shfl_sync(0xffffffffu, s[kt][0], srcA);
            float x1 = __shfl_sync(0xffffffffu, s[kt][1], srcA);
            float x2 = __shfl_sync(0xffffffffu, s[kt][2], srcA);
            float x3 = __shfl_sync(0xffffffffu, s[kt][3], srcA);
            float y0 = __shfl_sync(0xffffffffu, s[kt][0], srcB);
            float y1 = __shfl_sync(0xffffffffu, s[kt][1], srcB);
            float y2 = __shfl_sync(0xffffffffu, s[kt][2], srcB);
            float y3 = __shfl_sync(0xffffffffu, s[kt][3], srcB);
            uint32_t a0 = f2tf(odd ? x1 : x0);  // (row g,   col kt*8+t)
            uint32_t a1 = f2tf(odd ? x3 : x2);  // (row g+8, col kt*8+t)
            uint32_t a2 = f2tf(odd ? y1 : y0);  // (row g,   col kt*8+t+4)
            uint32_t a3 = f2tf(odd ? y3 : y2);  // (row g+8, col kt*8+t+4)
#pragma unroll
            for (int dt = 0; dt < 8; dt++) {
                uint32_t b0 = Vs[(kt * 8 + t) * 68 + dt * 8 + g];
                uint32_t b1 = Vs[(kt * 8 + t + 4) * 68 + dt * 8 + g];
                mma8(o[dt], a0, a1, a2, a3, b0, b1);
            }
        }
    }

    const float il_lo = 1.f / l_lo;
    const float il_hi = 1.f / l_hi;
#pragma unroll
    for (int dt = 0; dt < 8; dt++) {
        int col = colbase + dt * 8 + 2 * t;
        *(float2*)(g_AO + mrow * 256 + col) =
            make_float2(o[dt][0] * il_lo, o[dt][1] * il_lo);
        *(float2*)(g_AO + (mrow + 8) * 256 + col) =
            make_float2(o[dt][2] * il_hi, o[dt][3] * il_hi);
    }
}

// ---------------------------------------------------------------------------
extern "C" void kernel_launch(void* const* d_in, const int* in_sizes, int n_in,
                              void* d_out, int out_size) {
    (void)in_sizes; (void)n_in; (void)out_size;
    const float* x  = (const float*)d_in[0];
    const float* Wq = (const float*)d_in[1];
    const float* bq = (const float*)d_in[2];
    const float* Wk = (const float*)d_in[3];
    const float* bk = (const float*)d_in[4];
    const float* Wv = (const float*)d_in[5];
    const float* bv = (const float*)d_in[6];
    const float* Wo = (const float*)d_in[7];
    const float* bo = (const float*)d_in[8];

    qkv_kernel<<<dim3(NTOK / 128, DMODEL / 64, 3), 256>>>(x, Wq, bq, Wk, bk, Wv, bv);
    attn_kernel<<<dim3(NTOK / 128, 4), 256>>>();
    oproj_kernel<<<dim3(NTOK / 128, DMODEL / 64), 256>>>(Wo, bo, (float*)d_out);
}

// round 5
// speedup vs baseline: 1.0024x; 1.0024x over previous
#include <cuda_runtime.h>
#include <cstdint>

// ---------------------------------------------------------------------------
// Fused 4-head attention, N=8192, D=256, HD=64, TF32 mma.sync path.
// Stage 1: QKV projections (TF32 GEMM)  -> g_Q/g_K/g_V
// Stage 2: flash attention per (head, 128-query tile) -> g_AO
// Stage 3: output projection (same GEMM) -> d_out
// ---------------------------------------------------------------------------

#define NTOK 8192
#define DMODEL 256

__device__ float g_Q[NTOK * DMODEL];
__device__ float g_K[NTOK * DMODEL];
__device__ float g_V[NTOK * DMODEL];
__device__ float g_AO[NTOK * DMODEL];

__device__ __forceinline__ uint32_t f2tf(float f) {
    uint32_t r;
    asm("cvt.rna.tf32.f32 %0, %1;" : "=r"(r) : "f"(f));
    return r;
}

__device__ __forceinline__ void mma8(float* c,
                                     uint32_t a0, uint32_t a1, uint32_t a2, uint32_t a3,
                                     uint32_t b0, uint32_t b1) {
    asm("mma.sync.aligned.m16n8k8.row.col.f32.tf32.tf32.f32 "
        "{%0,%1,%2,%3}, {%4,%5,%6,%7}, {%8,%9}, {%0,%1,%2,%3};"
        : "+f"(c[0]), "+f"(c[1]), "+f"(c[2]), "+f"(c[3])
        : "r"(a0), "r"(a1), "r"(a2), "r"(a3), "r"(b0), "r"(b1));
}

// ---------------------------------------------------------------------------
// Generic C[M,256] = A[M,256] @ W[256,256] + bias, TF32, tile 128x64x32.
// Block = 256 threads (8 warps), warp w owns m-rows [16w, 16w+16), all 64 n.
// ---------------------------------------------------------------------------
__device__ __forceinline__ void gemm256(const float* __restrict__ A,
                                        const float* __restrict__ W,
                                        const float* __restrict__ bias,
                                        float* __restrict__ C) {
    __shared__ uint32_t As[128 * 36];   // [m][k], stride 36 (conflict-free frag reads)
    __shared__ uint32_t Ws[32 * 68];    // [k][n], stride 68

    const int tid = threadIdx.x;
    const int lane = tid & 31;
    const int w = tid >> 5;
    const int g = lane >> 2;   // groupID (row within frag)
    const int t = lane & 3;    // threadID in group
    const int m0 = blockIdx.x * 128;
    const int n0 = blockIdx.y * 64;

    float acc[8][4];
#pragma unroll
    for (int nt = 0; nt < 8; nt++)
#pragma unroll
        for (int i = 0; i < 4; i++) acc[nt][i] = 0.f;

    for (int kc = 0; kc < 256; kc += 32) {
        __syncthreads();
        // A tile: 128x32 -> 1024 float4, 4 per thread
#pragma unroll
        for (int r = 0; r < 4; r++) {
            int idx = tid + r * 256;
            int row = idx >> 3;
            int c4 = (idx & 7) * 4;
            float4 v = *(const float4*)(A + (m0 + row) * 256 + kc + c4);
            uint32_t* d = &As[row * 36 + c4];
            d[0] = f2tf(v.x); d[1] = f2tf(v.y); d[2] = f2tf(v.z); d[3] = f2tf(v.w);
        }
        // W tile: 32x64 -> 512 float4, 2 per thread
#pragma unroll
        for (int r = 0; r < 2; r++) {
            int idx = tid + r * 256;
            int kr = idx >> 4;
            int c4 = (idx & 15) * 4;
            float4 v = *(const float4*)(W + (kc + kr) * 256 + n0 + c4);
            uint32_t* d = &Ws[kr * 68 + c4];
            d[0] = f2tf(v.x); d[1] = f2tf(v.y); d[2] = f2tf(v.z); d[3] = f2tf(v.w);
        }
        __syncthreads();

#pragma unroll
        for (int kt = 0; kt < 4; kt++) {
            uint32_t a0 = As[(w * 16 + g) * 36 + kt * 8 + t];
            uint32_t a1 = As[(w * 16 + g + 8) * 36 + kt * 8 + t];
            uint32_t a2 = As[(w * 16 + g) * 36 + kt * 8 + t + 4];
            uint32_t a3 = As[(w * 16 + g + 8) * 36 + kt * 8 + t + 4];
#pragma unroll
            for (int nt = 0; nt < 8; nt++) {
                uint32_t b0 = Ws[(kt * 8 + t) * 68 + nt * 8 + g];
                uint32_t b1 = Ws[(kt * 8 + t + 4) * 68 + nt * 8 + g];
                mma8(acc[nt], a0, a1, a2, a3, b0, b1);
            }
        }
    }

    const int r0 = m0 + w * 16 + g;
#pragma unroll
    for (int nt = 0; nt < 8; nt++) {
        int col = n0 + nt * 8 + 2 * t;
        float bv0 = bias[col], bv1 = bias[col + 1];
        float2 v0 = make_float2(acc[nt][0] + bv0, acc[nt][1] + bv1);
        float2 v1 = make_float2(acc[nt][2] + bv0, acc[nt][3] + bv1);
        *(float2*)(C + r0 * 256 + col) = v0;
        *(float2*)(C + (r0 + 8) * 256 + col) = v1;
    }
}

__global__ void __launch_bounds__(256) qkv_kernel(const float* __restrict__ x,
                                                  const float* __restrict__ Wq, const float* __restrict__ bq,
                                                  const float* __restrict__ Wk, const float* __restrict__ bk,
                                                  const float* __restrict__ Wv, const float* __restrict__ bv) {
    if (blockIdx.z == 0)      gemm256(x, Wq, bq, g_Q);
    else if (blockIdx.z == 1) gemm256(x, Wk, bk, g_K);
    else                      gemm256(x, Wv, bv, g_V);
}

__global__ void __launch_bounds__(256) oproj_kernel(const float* __restrict__ Wo,
                                                    const float* __restrict__ bo,
                                                    float* __restrict__ out) {
    gemm256(g_AO, Wo, bo, out);
}

// ---------------------------------------------------------------------------
// Flash attention. Block = (128 queries, 1 head), 8 warps, each warp 16 rows.
// Key loop in 64-key chunks. Q frags live in registers for the whole kernel.
// ---------------------------------------------------------------------------
__global__ void __launch_bounds__(256) attn_kernel() {
    __shared__ uint32_t Ks[64 * 68];   // [j][d], stride 68
    __shared__ uint32_t Vs[64 * 68];   // [j][d], stride 68

    const int tid = threadIdx.x;
    const int lane = tid & 31;
    const int w = tid >> 5;
    const int g = lane >> 2;
    const int t = lane & 3;
    const int q0 = blockIdx.x * 128;
    const int h = blockIdx.y;
    const int colbase = h * 64;
    const int mrow = q0 + w * 16 + g;

    // Q fragments (scale 1/sqrt(64)=0.125 folded in): A layout m16n8k8
    uint32_t qf[8][4];
#pragma unroll
    for (int kt = 0; kt < 8; kt++) {
        int c = colbase + kt * 8 + t;
        qf[kt][0] = f2tf(g_Q[mrow * 256 + c] * 0.125f);
        qf[kt][1] = f2tf(g_Q[(mrow + 8) * 256 + c] * 0.125f);
        qf[kt][2] = f2tf(g_Q[mrow * 256 + c + 4] * 0.125f);
        qf[kt][3] = f2tf(g_Q[(mrow + 8) * 256 + c + 4] * 0.125f);
    }

    float o[8][4];
#pragma unroll
    for (int dt = 0; dt < 8; dt++)
#pragma unroll
        for (int i = 0; i < 4; i++) o[dt][i] = 0.f;

    float m_lo = -1e30f, m_hi = -1e30f, l_lo = 0.f, l_hi = 0.f;

    const int srcA = (lane & ~3) | (t >> 1);  // owner of cols {t}
    const int srcB = srcA + 2;                // owner of cols {t+4}

    for (int j0 = 0; j0 < NTOK; j0 += 64) {
        __syncthreads();
        // Stage K and V 64x64 tiles (cvt to tf32 on the way in)
#pragma unroll
        for (int r = 0; r < 4; r++) {
            int idx = tid + r * 256;
            int row = idx >> 4;
            int c4 = (idx & 15) * 4;
            float4 kv = *(const float4*)(g_K + (j0 + row) * 256 + colbase + c4);
            uint32_t* dk = &Ks[row * 68 + c4];
            dk[0] = f2tf(kv.x); dk[1] = f2tf(kv.y); dk[2] = f2tf(kv.z); dk[3] = f2tf(kv.w);
            float4 vv = *(const float4*)(g_V + (j0 + row) * 256 + colbase + c4);
            uint32_t* dv = &Vs[row * 68 + c4];
            dv[0] = f2tf(vv.x); dv[1] = f2tf(vv.y); dv[2] = f2tf(vv.z); dv[3] = f2tf(vv.w);
        }
        __syncthreads();

        // S = Q K^T  (n = key j, k = head dim d); B(k,n) = K[n][k] = Ks[j][d]
        float s[8][4];
#pragma unroll
        for (int nt = 0; nt < 8; nt++)
#pragma unroll
            for (int i = 0; i < 4; i++) s[nt][i] = 0.f;

#pragma unroll
        for (int kt = 0; kt < 8; kt++) {
#pragma unroll
            for (int nt = 0; nt < 8; nt++) {
                uint32_t b0 = Ks[(nt * 8 + g) * 68 + kt * 8 + t];
                uint32_t b1 = Ks[(nt * 8 + g) * 68 + kt * 8 + t + 4];
                mma8(s[nt], qf[kt][0], qf[kt][1], qf[kt][2], qf[kt][3], b0, b1);
            }
        }

        // Online softmax (rows lo = g, hi = g+8; stats within a quad)
        float rmax_lo = -1e30f, rmax_hi = -1e30f;
#pragma unroll
        for (int nt = 0; nt < 8; nt++) {
            rmax_lo = fmaxf(rmax_lo, fmaxf(s[nt][0], s[nt][1]));
            rmax_hi = fmaxf(rmax_hi, fmaxf(s[nt][2], s[nt][3]));
        }
        rmax_lo = fmaxf(rmax_lo, __shfl_xor_sync(0xffffffffu, rmax_lo, 1));
        rmax_lo = fmaxf(rmax_lo, __shfl_xor_sync(0xffffffffu, rmax_lo, 2));
        rmax_hi = fmaxf(rmax_hi, __shfl_xor_sync(0xffffffffu, rmax_hi, 1));
        rmax_hi = fmaxf(rmax_hi, __shfl_xor_sync(0xffffffffu, rmax_hi, 2));

        float mn_lo = fmaxf(m_lo, rmax_lo);
        float mn_hi = fmaxf(m_hi, rmax_hi);
        float f_lo = __expf(m_lo - mn_lo);
        float f_hi = __expf(m_hi - mn_hi);
        m_lo = mn_lo; m_hi = mn_hi;

        float rs_lo = 0.f, rs_hi = 0.f;
#pragma unroll
        for (int nt = 0; nt < 8; nt++) {
            s[nt][0] = __expf(s[nt][0] - m_lo);
            s[nt][1] = __expf(s[nt][1] - m_lo);
            s[nt][2] = __expf(s[nt][2] - m_hi);
            s[nt][3] = __expf(s[nt][3] - m_hi);
            rs_lo += s[nt][0] + s[nt][1];
            rs_hi += s[nt][2] + s[nt][3];
        }
        rs_lo += __shfl_xor_sync(0xffffffffu, rs_lo, 1);
        rs_lo += __shfl_xor_sync(0xffffffffu, rs_lo, 2);
        rs_hi += __shfl_xor_sync(0xffffffffu, rs_hi, 1);
        rs_hi += __shfl_xor_sync(0xffffffffu, rs_hi, 2);
        l_lo = l_lo * f_lo + rs_lo;
        l_hi = l_hi * f_hi + rs_hi;

#pragma unroll
        for (int dt = 0; dt < 8; dt++) {
            o[dt][0] *= f_lo; o[dt][1] *= f_lo;
            o[dt][2] *= f_hi; o[dt][3] *= f_hi;
        }

        // P(C-layout) -> A-fragments via intra-quad shuffles, then O += P V.
        // B(k=j, n=d) = V[j][d] = Vs (read transposed in-place).
        const bool odd = (t & 1);
#pragma unroll
        for (int kt = 0; kt < 8; kt++) {
            float x0 = __shfl_sync(0xffffffffu, s[kt][0], srcA);
            float x1 = __shfl_sync(0xffffffffu, s[kt][1], srcA);
            float x2 = __shfl_sync(0xffffffffu, s[kt][2], srcA);
            float x3 = __shfl_sync(0xffffffffu, s[kt][3], srcA);
            float y0 = __shfl_sync(0xffffffffu, s[kt][0], srcB);
            float y1 = __shfl_sync(0xffffffffu, s[kt][1], srcB);
            float y2 = __shfl_sync(0xffffffffu, s[kt][2], srcB);
            float y3 = __shfl_sync(0xffffffffu, s[kt][3], srcB);
            uint32_t a0 = f2tf(odd ? x1 : x0);  // (row g,   col kt*8+t)
            uint32_t a1 = f2tf(odd ? x3 : x2);  // (row g+8, col kt*8+t)
            uint32_t a2 = f2tf(odd ? y1 : y0);  // (row g,   col kt*8+t+4)
            uint32_t a3 = f2tf(odd ? y3 : y2);  // (row g+8, col kt*8+t+4)
#pragma unroll
            for (int dt = 0; dt < 8; dt++) {
                uint32_t b0 = Vs[(kt * 8 + t) * 68 + dt * 8 + g];
                uint32_t b1 = Vs[(kt * 8 + t + 4) * 68 + dt * 8 + g];
                mma8(o[dt], a0, a1, a2, a3, b0, b1);
            }
        }
    }

    const float il_lo = 1.f / l_lo;
    const float il_hi = 1.f / l_hi;
#pragma unroll
    for (int dt = 0; dt < 8; dt++) {
        int col = colbase + dt * 8 + 2 * t;
        *(float2*)(g_AO + mrow * 256 + col) =
            make_float2(o[dt][0] * il_lo, o[dt][1] * il_lo);
        *(float2*)(g_AO + (mrow + 8) * 256 + col) =
            make_float2(o[dt][2] * il_hi, o[dt][3] * il_hi);
    }
}

// ---------------------------------------------------------------------------
extern "C" void kernel_launch(void* const* d_in, const int* in_sizes, int n_in,
                              void* d_out, int out_size) {
    (void)in_sizes; (void)n_in; (void)out_size;
    const float* x  = (const float*)d_in[0];
    const float* Wq = (const float*)d_in[1];
    const float* bq = (const float*)d_in[2];
    const float* Wk = (const float*)d_in[3];
    const float* bk = (const float*)d_in[4];
    const float* Wv = (const float*)d_in[5];
    const float* bv = (const float*)d_in[6];
    const float* Wo = (const float*)d_in[7];
    const float* bo = (const float*)d_in[8];

    qkv_kernel<<<dim3(NTOK / 128, DMODEL / 64, 3), 256>>>(x, Wq, bq, Wk, bk, Wv, bv);
    attn_kernel<<<dim3(NTOK / 128, 4), 256>>>();
    oproj_kernel<<<dim3(NTOK / 128, DMODEL / 64), 256>>>(Wo, bo, (float*)d_out);
}